// round 13
// baseline (speedup 1.0000x reference)
#include <cuda_runtime.h>
#include <cuda_fp16.h>
#include <cstdint>

// Problem constants (match reference)
#define N_USERS 200000
#define N_ITEMS 400000
#define N_NODES 600000
#define EMB_DIM 128
#define N_EDGES 3000000
#define VEC4_PER_ROW 32
#define TOTAL_F ((size_t)N_NODES * EMB_DIM)   // 76.8M elems
#define TOTAL_V4 (TOTAL_F / 4)

// Pin only the first PIN_SPLIT rows (99.8 MB) in L2: pinned set must be
// smaller than the 126 MB L2 or evict_last thrashes itself.
#define PIN_SPLIT 390000

#define SCAN_BLOCK 1024
#define N_SCAN_BLOCKS ((N_NODES + SCAN_BLOCK - 1) / SCAN_BLOCK)  // 586

// Static scratch (allowed: __device__ globals; zero-init on load)
__device__ __align__(256) __half g_bufX[TOTAL_F];   // fp16 inputs, 153.6 MB
__device__ __align__(256) __half g_bufA[TOTAL_F];
__device__ __align__(256) __half g_bufB[TOTAL_F];
__device__ int  g_count[N_NODES];    // re-zeroed every replay by scan1
__device__ int  g_offsetL[N_NODES];  // block-local exclusive scan
__device__ int  g_pos[N_NODES];
__device__ int  g_bsum[SCAN_BLOCK];  // >= N_SCAN_BLOCKS
__device__ int2 g_pair[N_EDGES];     // (col, val-as-int), CSR order

// ---------------------------------------------------------------------------
// Launch 1: histogram + fp32->fp16 input conversion (grid-stride)
// ---------------------------------------------------------------------------
__global__ void hist_convert_kernel(const int* __restrict__ rows,
                                    int* __restrict__ count,
                                    const float4* __restrict__ user,
                                    const float4* __restrict__ item,
                                    uint2* __restrict__ X2) {
    size_t tid = (size_t)blockIdx.x * blockDim.x + threadIdx.x;
    if (tid < N_EDGES) atomicAdd(&count[rows[tid]], 1);

    const size_t user_v4 = (size_t)N_USERS * VEC4_PER_ROW;
    size_t stride = (size_t)gridDim.x * blockDim.x;
    for (size_t i = tid; i < TOTAL_V4; i += stride) {
        float4 v = (i < user_v4) ? __ldcs(user + i) : __ldcs(item + i - user_v4);
        __half2 h0 = __floats2half2_rn(v.x, v.y);
        __half2 h1 = __floats2half2_rn(v.z, v.w);
        uint2 raw;
        raw.x = *reinterpret_cast<unsigned*>(&h0);
        raw.y = *reinterpret_cast<unsigned*>(&h1);
        __stcs(X2 + i, raw);   // streaming
    }
}

// ---------------------------------------------------------------------------
// Launch 2: block-local exclusive scan; zeroes count; seeds pos
// ---------------------------------------------------------------------------
__global__ void scan1_kernel(int* __restrict__ count,
                             int* __restrict__ offsetL,
                             int* __restrict__ pos,
                             int* __restrict__ bsum) {
    __shared__ int sh[SCAN_BLOCK];
    int i = blockIdx.x * SCAN_BLOCK + threadIdx.x;
    int v = (i < N_NODES) ? count[i] : 0;
    if (i < N_NODES) count[i] = 0;   // restore replay invariant
    sh[threadIdx.x] = v;
    __syncthreads();
    #pragma unroll
    for (int d = 1; d < SCAN_BLOCK; d <<= 1) {
        int t = (threadIdx.x >= d) ? sh[threadIdx.x - d] : 0;
        __syncthreads();
        sh[threadIdx.x] += t;
        __syncthreads();
    }
    if (i < N_NODES) {
        int excl = sh[threadIdx.x] - v;
        offsetL[i] = excl;
        pos[i] = excl;
    }
    if (threadIdx.x == SCAN_BLOCK - 1) bsum[blockIdx.x] = sh[SCAN_BLOCK - 1];
}

// ---------------------------------------------------------------------------
// Launch 3: exclusive scan of block sums (single block)
// ---------------------------------------------------------------------------
__global__ void scan2_kernel(int* __restrict__ bsum, int nb) {
    __shared__ int sh[SCAN_BLOCK];
    int v = (threadIdx.x < nb) ? bsum[threadIdx.x] : 0;
    sh[threadIdx.x] = v;
    __syncthreads();
    #pragma unroll
    for (int d = 1; d < SCAN_BLOCK; d <<= 1) {
        int t = (threadIdx.x >= d) ? sh[threadIdx.x - d] : 0;
        __syncthreads();
        sh[threadIdx.x] += t;
        __syncthreads();
    }
    if (threadIdx.x < nb) bsum[threadIdx.x] = sh[threadIdx.x] - v;  // exclusive
}

// ---------------------------------------------------------------------------
// Launch 4: permute edges into CSR order (global offset = local + bsum)
// ---------------------------------------------------------------------------
__global__ void permute_kernel(const int* __restrict__ rows,
                               const int* __restrict__ cols,
                               const float* __restrict__ vals,
                               int* __restrict__ pos,
                               const int* __restrict__ bsum,
                               int2* __restrict__ pair) {
    int e = blockIdx.x * blockDim.x + threadIdx.x;
    if (e >= N_EDGES) return;
    int r = rows[e];
    int p = atomicAdd(&pos[r], 1) + __ldg(&bsum[r >> 10]);
    int2 pr;
    pr.x = cols[e];
    pr.y = __float_as_int(vals[e]);
    __stcs(pair + p, pr);    // streaming scatter
}

// ---------------------------------------------------------------------------
// Gather: 32B (256-bit) load; rows < PIN_SPLIT pinned via L2::evict_last
// (pinned set = 99.8 MB < 126 MB L2), rest normal priority. FMA into 16 accs.
// ---------------------------------------------------------------------------
__device__ __forceinline__ void gather_acc(const __half* __restrict__ srcH,
                                           int col, int sub, float v,
                                           float* acc) {
    const char* p = reinterpret_cast<const char*>(srcH)
                    + ((size_t)col << 8) + (sub << 5);
    uint32_t q0, q1, q2, q3, q4, q5, q6, q7;
    if (col < PIN_SPLIT) {
        asm volatile(
            "ld.global.nc.L2::evict_last.v8.b32 {%0,%1,%2,%3,%4,%5,%6,%7}, [%8];"
            : "=r"(q0), "=r"(q1), "=r"(q2), "=r"(q3),
              "=r"(q4), "=r"(q5), "=r"(q6), "=r"(q7)
            : "l"(p));
    } else {
        asm volatile(
            "ld.global.nc.v8.b32 {%0,%1,%2,%3,%4,%5,%6,%7}, [%8];"
            : "=r"(q0), "=r"(q1), "=r"(q2), "=r"(q3),
              "=r"(q4), "=r"(q5), "=r"(q6), "=r"(q7)
            : "l"(p));
    }
    uint32_t q[8] = {q0, q1, q2, q3, q4, q5, q6, q7};
    #pragma unroll
    for (int i = 0; i < 8; ++i) {
        __half2 h = *reinterpret_cast<__half2*>(&q[i]);
        float2 f = __half22float2(h);
        acc[2 * i]     += v * f.x;
        acc[2 * i + 1] += v * f.y;
    }
}

__device__ __forceinline__ void unpack16(uint4 lo, uint4 hi, float* f) {
    uint32_t q[8] = {lo.x, lo.y, lo.z, lo.w, hi.x, hi.y, hi.z, hi.w};
    #pragma unroll
    for (int i = 0; i < 8; ++i) {
        __half2 h = *reinterpret_cast<__half2*>(&q[i]);
        float2 t = __half22float2(h);
        f[2 * i] = t.x;
        f[2 * i + 1] = t.y;
    }
}

// ---------------------------------------------------------------------------
// Launches 5-7: pull SpMM. One 8-lane group per row; lane owns 16 elements
// (32B fp16). Single-wave predicated loop: all ceil(deg/4) blocks issue 4
// clamped pair loads at once; gathers predicated (uniform per group).
// FUSED (layer 3): out = 0.25*(x0_fp32 + A + B + y)
// ---------------------------------------------------------------------------
template <bool FUSED>
__global__ void __launch_bounds__(256)
spmm_kernel(const int* __restrict__ offsetL,
            const int* __restrict__ bsum,
            const int2* __restrict__ pair,
            const __half* __restrict__ xH,    // gather src (fp16)
            __half* __restrict__ dstH,        // layer output (fp16)
            const float4* __restrict__ u,     // FUSED: user embs fp32
            const float4* __restrict__ it,    // FUSED: item embs fp32
            const __half* __restrict__ accA,  // FUSED: layer-1 out
            const __half* __restrict__ accB,  // FUSED: layer-2 out
            float4* __restrict__ out) {       // FUSED: final out fp32
    int sub = threadIdx.x & 7;                            // lane within group
    int r = (blockIdx.x * blockDim.x + threadIdx.x) >> 3; // group id = row
    if (r >= N_NODES) return;

    int j = __ldg(offsetL + r) + __ldg(bsum + (r >> 10));
    int end = (r == N_NODES - 1)
                  ? N_EDGES
                  : __ldg(offsetL + r + 1) + __ldg(bsum + ((r + 1) >> 10));

    float acc[16];
    #pragma unroll
    for (int k = 0; k < 16; ++k) acc[k] = 0.f;

    // Single-wave: 4 clamped pair loads per block, predicated gathers.
    #pragma unroll 1
    for (; j < end; j += 4) {
        int last = end - 1;
        int j1 = (j + 1 < last) ? j + 1 : last;
        int j2 = (j + 2 < last) ? j + 2 : last;
        int j3 = (j + 3 < last) ? j + 3 : last;
        int2 e0 = __ldcs(pair + j);
        int2 e1 = __ldcs(pair + j1);
        int2 e2 = __ldcs(pair + j2);
        int2 e3 = __ldcs(pair + j3);
        gather_acc(xH, e0.x, sub, __int_as_float(e0.y), acc);
        if (j + 1 < end) gather_acc(xH, e1.x, sub, __int_as_float(e1.y), acc);
        if (j + 2 < end) gather_acc(xH, e2.x, sub, __int_as_float(e2.y), acc);
        if (j + 3 < end) gather_acc(xH, e3.x, sub, __int_as_float(e3.y), acc);
    }

    if (FUSED) {
        const uint4* aRow = reinterpret_cast<const uint4*>(accA + (size_t)r * EMB_DIM);
        const uint4* bRow = reinterpret_cast<const uint4*>(accB + (size_t)r * EMB_DIM);
        float a[16], b[16];
        unpack16(__ldcs(aRow + 2 * sub), __ldcs(aRow + 2 * sub + 1), a);
        unpack16(__ldcs(bRow + 2 * sub), __ldcs(bRow + 2 * sub + 1), b);

        const float4* xr = (r < N_USERS)
                               ? (u + (size_t)r * VEC4_PER_ROW)
                               : (it + (size_t)(r - N_USERS) * VEC4_PER_ROW);
        float4* orow = out + (size_t)r * VEC4_PER_ROW + 4 * sub;
        #pragma unroll
        for (int q = 0; q < 4; ++q) {
            float4 x0 = __ldcs(xr + 4 * sub + q);
            float4 o;
            o.x = 0.25f * (x0.x + a[4 * q + 0] + b[4 * q + 0] + acc[4 * q + 0]);
            o.y = 0.25f * (x0.y + a[4 * q + 1] + b[4 * q + 1] + acc[4 * q + 1]);
            o.z = 0.25f * (x0.z + a[4 * q + 2] + b[4 * q + 2] + acc[4 * q + 2]);
            o.w = 0.25f * (x0.w + a[4 * q + 3] + b[4 * q + 3] + acc[4 * q + 3]);
            __stcs(orow + q, o);
        }
    } else {
        uint32_t q[8];
        #pragma unroll
        for (int i = 0; i < 8; ++i) {
            __half2 h = __floats2half2_rn(acc[2 * i], acc[2 * i + 1]);
            q[i] = *reinterpret_cast<unsigned*>(&h);
        }
        uint4* drow = reinterpret_cast<uint4*>(dstH + (size_t)r * EMB_DIM) + 2 * sub;
        __stcs(drow, make_uint4(q[0], q[1], q[2], q[3]));
        __stcs(drow + 1, make_uint4(q[4], q[5], q[6], q[7]));
    }
}

extern "C" void kernel_launch(void* const* d_in, const int* in_sizes, int n_in,
                              void* d_out, int out_size) {
    const float4* emb_user = (const float4*)d_in[0];
    const float4* emb_item = (const float4*)d_in[1];
    const int* edge_row = (const int*)d_in[2];
    const int* edge_col = (const int*)d_in[3];
    const float* edge_val = (const float*)d_in[4];
    float4* out = (float4*)d_out;

    __half *X, *A, *B;
    int *count_, *offsetL_, *pos_, *bsum_;
    int2 *pair_;
    cudaGetSymbolAddress((void**)&X, g_bufX);
    cudaGetSymbolAddress((void**)&A, g_bufA);
    cudaGetSymbolAddress((void**)&B, g_bufB);
    cudaGetSymbolAddress((void**)&count_, g_count);
    cudaGetSymbolAddress((void**)&offsetL_, g_offsetL);
    cudaGetSymbolAddress((void**)&pos_, g_pos);
    cudaGetSymbolAddress((void**)&bsum_, g_bsum);
    cudaGetSymbolAddress((void**)&pair_, g_pair);

    const int T = 256;
    const int gridEdge = (N_EDGES + T - 1) / T;
    const int TS = 256;                                   // 32 rows per block
    const int gridRow = (int)(((size_t)N_NODES * 8 + TS - 1) / TS);

    // ---- build: histogram(+convert), two-kernel scan, permute ----
    hist_convert_kernel<<<gridEdge, T>>>(edge_row, count_,
                                         emb_user, emb_item, (uint2*)X);
    scan1_kernel<<<N_SCAN_BLOCKS, SCAN_BLOCK>>>(count_, offsetL_, pos_, bsum_);
    scan2_kernel<<<1, SCAN_BLOCK>>>(bsum_, N_SCAN_BLOCKS);
    permute_kernel<<<gridEdge, T>>>(edge_row, edge_col, edge_val,
                                    pos_, bsum_, pair_);

    // ---- Layer 1: gather X -> A ----
    spmm_kernel<false><<<gridRow, TS>>>(offsetL_, bsum_, pair_, X, A,
                                        nullptr, nullptr, nullptr, nullptr,
                                        nullptr);
    // ---- Layer 2: gather A -> B ----
    spmm_kernel<false><<<gridRow, TS>>>(offsetL_, bsum_, pair_, A, B,
                                        nullptr, nullptr, nullptr, nullptr,
                                        nullptr);
    // ---- Layer 3 fused: gather B, out = 0.25*(x0 + A + B + y) ----
    spmm_kernel<true><<<gridRow, TS>>>(offsetL_, bsum_, pair_, B, nullptr,
                                       emb_user, emb_item, A, B, out);
}

// round 14
// speedup vs baseline: 1.0545x; 1.0545x over previous
#include <cuda_runtime.h>
#include <cuda_fp16.h>
#include <cstdint>

// Problem constants (match reference)
#define N_USERS 200000
#define N_ITEMS 400000
#define N_NODES 600000
#define EMB_DIM 128
#define N_EDGES 3000000
#define VEC4_PER_ROW 32
#define TOTAL_F ((size_t)N_NODES * EMB_DIM)   // 76.8M elems
#define TOTAL_V4 (TOTAL_F / 4)

#define SCAN_BLOCK 1024
#define N_SCAN_BLOCKS ((N_NODES + SCAN_BLOCK - 1) / SCAN_BLOCK)  // 586

// Static scratch (allowed: __device__ globals; zero-init on load)
__device__ __align__(256) __half g_bufX[TOTAL_F];   // fp16 inputs, 153.6 MB
__device__ __align__(256) __half g_bufA[TOTAL_F];
__device__ __align__(256) __half g_bufB[TOTAL_F];
__device__ int  g_count[N_NODES];    // re-zeroed every replay by scan1
__device__ int  g_offsetL[N_NODES];  // block-local exclusive scan
__device__ int  g_pos[N_NODES];
__device__ int  g_bsum[SCAN_BLOCK];  // >= N_SCAN_BLOCKS
__device__ int2 g_pair[N_EDGES];     // (col, val-as-int), CSR order

// ---------------------------------------------------------------------------
// Launch 1: histogram + fp32->fp16 input conversion (grid-stride)
// ---------------------------------------------------------------------------
__global__ void hist_convert_kernel(const int* __restrict__ rows,
                                    int* __restrict__ count,
                                    const float4* __restrict__ user,
                                    const float4* __restrict__ item,
                                    uint2* __restrict__ X2) {
    size_t tid = (size_t)blockIdx.x * blockDim.x + threadIdx.x;
    if (tid < N_EDGES) atomicAdd(&count[rows[tid]], 1);

    const size_t user_v4 = (size_t)N_USERS * VEC4_PER_ROW;
    size_t stride = (size_t)gridDim.x * blockDim.x;
    for (size_t i = tid; i < TOTAL_V4; i += stride) {
        float4 v = (i < user_v4) ? __ldcs(user + i) : __ldcs(item + i - user_v4);
        __half2 h0 = __floats2half2_rn(v.x, v.y);
        __half2 h1 = __floats2half2_rn(v.z, v.w);
        uint2 raw;
        raw.x = *reinterpret_cast<unsigned*>(&h0);
        raw.y = *reinterpret_cast<unsigned*>(&h1);
        __stcs(X2 + i, raw);   // streaming
    }
}

// ---------------------------------------------------------------------------
// Launch 2: block-local exclusive scan; zeroes count; seeds pos
// ---------------------------------------------------------------------------
__global__ void scan1_kernel(int* __restrict__ count,
                             int* __restrict__ offsetL,
                             int* __restrict__ pos,
                             int* __restrict__ bsum) {
    __shared__ int sh[SCAN_BLOCK];
    int i = blockIdx.x * SCAN_BLOCK + threadIdx.x;
    int v = (i < N_NODES) ? count[i] : 0;
    if (i < N_NODES) count[i] = 0;   // restore replay invariant
    sh[threadIdx.x] = v;
    __syncthreads();
    #pragma unroll
    for (int d = 1; d < SCAN_BLOCK; d <<= 1) {
        int t = (threadIdx.x >= d) ? sh[threadIdx.x - d] : 0;
        __syncthreads();
        sh[threadIdx.x] += t;
        __syncthreads();
    }
    if (i < N_NODES) {
        int excl = sh[threadIdx.x] - v;
        offsetL[i] = excl;
        pos[i] = excl;
    }
    if (threadIdx.x == SCAN_BLOCK - 1) bsum[blockIdx.x] = sh[SCAN_BLOCK - 1];
}

// ---------------------------------------------------------------------------
// Launch 3: exclusive scan of block sums (single block)
// ---------------------------------------------------------------------------
__global__ void scan2_kernel(int* __restrict__ bsum, int nb) {
    __shared__ int sh[SCAN_BLOCK];
    int v = (threadIdx.x < nb) ? bsum[threadIdx.x] : 0;
    sh[threadIdx.x] = v;
    __syncthreads();
    #pragma unroll
    for (int d = 1; d < SCAN_BLOCK; d <<= 1) {
        int t = (threadIdx.x >= d) ? sh[threadIdx.x - d] : 0;
        __syncthreads();
        sh[threadIdx.x] += t;
        __syncthreads();
    }
    if (threadIdx.x < nb) bsum[threadIdx.x] = sh[threadIdx.x] - v;  // exclusive
}

// ---------------------------------------------------------------------------
// Launch 4: permute edges into CSR order (global offset = local + bsum)
// ---------------------------------------------------------------------------
__global__ void permute_kernel(const int* __restrict__ rows,
                               const int* __restrict__ cols,
                               const float* __restrict__ vals,
                               int* __restrict__ pos,
                               const int* __restrict__ bsum,
                               int2* __restrict__ pair) {
    int e = blockIdx.x * blockDim.x + threadIdx.x;
    if (e >= N_EDGES) return;
    int r = rows[e];
    int p = atomicAdd(&pos[r], 1) + __ldg(&bsum[r >> 10]);
    int2 pr;
    pr.x = cols[e];
    pr.y = __float_as_int(vals[e]);
    __stcs(pair + p, pr);    // streaming scatter
}

// ---------------------------------------------------------------------------
// Gather: 32B (256-bit) load + L2 evict_last. Per half-D pass the touched
// working set is 76.8 MB < 126 MB L2, so the pin is fully effective.
// ---------------------------------------------------------------------------
__device__ __forceinline__ void gather_acc(const __half* __restrict__ srcH,
                                           int col, int laneByte, float v,
                                           float* acc) {
    const char* p = reinterpret_cast<const char*>(srcH)
                    + ((size_t)col << 8) + laneByte;
    uint32_t q0, q1, q2, q3, q4, q5, q6, q7;
    asm volatile(
        "ld.global.nc.L2::evict_last.v8.b32 {%0,%1,%2,%3,%4,%5,%6,%7}, [%8];"
        : "=r"(q0), "=r"(q1), "=r"(q2), "=r"(q3),
          "=r"(q4), "=r"(q5), "=r"(q6), "=r"(q7)
        : "l"(p));
    uint32_t q[8] = {q0, q1, q2, q3, q4, q5, q6, q7};
    #pragma unroll
    for (int i = 0; i < 8; ++i) {
        __half2 h = *reinterpret_cast<__half2*>(&q[i]);
        float2 f = __half22float2(h);
        acc[2 * i]     += v * f.x;
        acc[2 * i + 1] += v * f.y;
    }
}

__device__ __forceinline__ void unpack16(uint4 lo, uint4 hi, float* f) {
    uint32_t q[8] = {lo.x, lo.y, lo.z, lo.w, hi.x, hi.y, hi.z, hi.w};
    #pragma unroll
    for (int i = 0; i < 8; ++i) {
        __half2 h = *reinterpret_cast<__half2*>(&q[i]);
        float2 t = __half22float2(h);
        f[2 * i] = t.x;
        f[2 * i + 1] = t.y;
    }
}

// ---------------------------------------------------------------------------
// Launches 5-10: pull SpMM over HALF the feature dim per launch.
// One 4-lane group per row; lane owns 16 elements (32B fp16) of the half.
// half = 0: bytes [0,128) of each row; half = 1: bytes [128,256).
// Loop = R9's proven x2 unroll + remainder.
// FUSED (layer 3): out = 0.25*(x0_fp32 + A + B + y), this half's columns.
// ---------------------------------------------------------------------------
template <bool FUSED>
__global__ void __launch_bounds__(256)
spmm_kernel(const int* __restrict__ offsetL,
            const int* __restrict__ bsum,
            const int2* __restrict__ pair,
            const __half* __restrict__ xH,    // gather src (fp16)
            __half* __restrict__ dstH,        // layer output (fp16)
            const float4* __restrict__ u,     // FUSED: user embs fp32
            const float4* __restrict__ it,    // FUSED: item embs fp32
            const __half* __restrict__ accA,  // FUSED: layer-1 out
            const __half* __restrict__ accB,  // FUSED: layer-2 out
            float4* __restrict__ out,         // FUSED: final out fp32
            int half) {                       // which 128B half of rows
    int sub = threadIdx.x & 3;                            // lane within group
    int r = (blockIdx.x * blockDim.x + threadIdx.x) >> 2; // group id = row
    if (r >= N_NODES) return;

    int laneByte = (half << 7) + (sub << 5);   // byte offset within 256B row

    int j = __ldg(offsetL + r) + __ldg(bsum + (r >> 10));
    int end = (r == N_NODES - 1)
                  ? N_EDGES
                  : __ldg(offsetL + r + 1) + __ldg(bsum + ((r + 1) >> 10));

    float acc[16];
    #pragma unroll
    for (int k = 0; k < 16; ++k) acc[k] = 0.f;

    #pragma unroll 1
    for (; j + 2 <= end; j += 2) {
        int2 e0 = __ldcs(pair + j);        // 4 lanes same addr: broadcast
        int2 e1 = __ldcs(pair + j + 1);
        gather_acc(xH, e0.x, laneByte, __int_as_float(e0.y), acc);
        gather_acc(xH, e1.x, laneByte, __int_as_float(e1.y), acc);
    }
    if (j < end) {
        int2 e0 = __ldcs(pair + j);
        gather_acc(xH, e0.x, laneByte, __int_as_float(e0.y), acc);
    }

    // Row-local uint4 index of this lane's 32B: half*8 + sub*2
    int v4idx = (half << 3) + (sub << 1);

    if (FUSED) {
        const uint4* aRow = reinterpret_cast<const uint4*>(accA + (size_t)r * EMB_DIM);
        const uint4* bRow = reinterpret_cast<const uint4*>(accB + (size_t)r * EMB_DIM);
        float a[16], b[16];
        unpack16(__ldcs(aRow + v4idx), __ldcs(aRow + v4idx + 1), a);
        unpack16(__ldcs(bRow + v4idx), __ldcs(bRow + v4idx + 1), b);

        const float4* xr = (r < N_USERS)
                               ? (u + (size_t)r * VEC4_PER_ROW)
                               : (it + (size_t)(r - N_USERS) * VEC4_PER_ROW);
        // lane owns float4s [16*half + 4*sub, +4) of the output row
        int fbase = (half << 4) + (sub << 2);
        float4* orow = out + (size_t)r * VEC4_PER_ROW + fbase;
        #pragma unroll
        for (int q = 0; q < 4; ++q) {
            float4 x0 = __ldcs(xr + fbase + q);
            float4 o;
            o.x = 0.25f * (x0.x + a[4 * q + 0] + b[4 * q + 0] + acc[4 * q + 0]);
            o.y = 0.25f * (x0.y + a[4 * q + 1] + b[4 * q + 1] + acc[4 * q + 1]);
            o.z = 0.25f * (x0.z + a[4 * q + 2] + b[4 * q + 2] + acc[4 * q + 2]);
            o.w = 0.25f * (x0.w + a[4 * q + 3] + b[4 * q + 3] + acc[4 * q + 3]);
            __stcs(orow + q, o);
        }
    } else {
        uint32_t q[8];
        #pragma unroll
        for (int i = 0; i < 8; ++i) {
            __half2 h = __floats2half2_rn(acc[2 * i], acc[2 * i + 1]);
            q[i] = *reinterpret_cast<unsigned*>(&h);
        }
        uint4* drow = reinterpret_cast<uint4*>(dstH + (size_t)r * EMB_DIM) + v4idx;
        __stcs(drow, make_uint4(q[0], q[1], q[2], q[3]));
        __stcs(drow + 1, make_uint4(q[4], q[5], q[6], q[7]));
    }
}

extern "C" void kernel_launch(void* const* d_in, const int* in_sizes, int n_in,
                              void* d_out, int out_size) {
    const float4* emb_user = (const float4*)d_in[0];
    const float4* emb_item = (const float4*)d_in[1];
    const int* edge_row = (const int*)d_in[2];
    const int* edge_col = (const int*)d_in[3];
    const float* edge_val = (const float*)d_in[4];
    float4* out = (float4*)d_out;

    __half *X, *A, *B;
    int *count_, *offsetL_, *pos_, *bsum_;
    int2 *pair_;
    cudaGetSymbolAddress((void**)&X, g_bufX);
    cudaGetSymbolAddress((void**)&A, g_bufA);
    cudaGetSymbolAddress((void**)&B, g_bufB);
    cudaGetSymbolAddress((void**)&count_, g_count);
    cudaGetSymbolAddress((void**)&offsetL_, g_offsetL);
    cudaGetSymbolAddress((void**)&pos_, g_pos);
    cudaGetSymbolAddress((void**)&bsum_, g_bsum);
    cudaGetSymbolAddress((void**)&pair_, g_pair);

    const int T = 256;
    const int gridEdge = (N_EDGES + T - 1) / T;
    const int TS = 256;                                   // 64 rows per block
    const int gridRow = (int)(((size_t)N_NODES * 4 + TS - 1) / TS);

    // ---- build: histogram(+convert), two-kernel scan, permute ----
    hist_convert_kernel<<<gridEdge, T>>>(edge_row, count_,
                                         emb_user, emb_item, (uint2*)X);
    scan1_kernel<<<N_SCAN_BLOCKS, SCAN_BLOCK>>>(count_, offsetL_, pos_, bsum_);
    scan2_kernel<<<1, SCAN_BLOCK>>>(bsum_, N_SCAN_BLOCKS);
    permute_kernel<<<gridEdge, T>>>(edge_row, edge_col, edge_val,
                                    pos_, bsum_, pair_);

    // ---- Layer 1: gather X -> A (two half-D passes) ----
    spmm_kernel<false><<<gridRow, TS>>>(offsetL_, bsum_, pair_, X, A,
                                        nullptr, nullptr, nullptr, nullptr,
                                        nullptr, 0);
    spmm_kernel<false><<<gridRow, TS>>>(offsetL_, bsum_, pair_, X, A,
                                        nullptr, nullptr, nullptr, nullptr,
                                        nullptr, 1);
    // ---- Layer 2: gather A -> B ----
    spmm_kernel<false><<<gridRow, TS>>>(offsetL_, bsum_, pair_, A, B,
                                        nullptr, nullptr, nullptr, nullptr,
                                        nullptr, 0);
    spmm_kernel<false><<<gridRow, TS>>>(offsetL_, bsum_, pair_, A, B,
                                        nullptr, nullptr, nullptr, nullptr,
                                        nullptr, 1);
    // ---- Layer 3 fused: gather B, out = 0.25*(x0 + A + B + y) ----
    spmm_kernel<true><<<gridRow, TS>>>(offsetL_, bsum_, pair_, B, nullptr,
                                       emb_user, emb_item, A, B, out, 0);
    spmm_kernel<true><<<gridRow, TS>>>(offsetL_, bsum_, pair_, B, nullptr,
                                       emb_user, emb_item, A, B, out, 1);
}

// round 15
// speedup vs baseline: 1.0969x; 1.0402x over previous
#include <cuda_runtime.h>
#include <cuda_fp16.h>
#include <cstdint>

// Problem constants (match reference)
#define N_USERS 200000
#define N_ITEMS 400000
#define N_NODES 600000
#define EMB_DIM 128
#define N_EDGES 3000000
#define VEC4_PER_ROW 32
#define TOTAL_F ((size_t)N_NODES * EMB_DIM)   // 76.8M elems
#define TOTAL_V4 (TOTAL_F / 4)

#define SCAN_BLOCK 1024
#define N_SCAN_BLOCKS ((N_NODES + SCAN_BLOCK - 1) / SCAN_BLOCK)  // 586

// Static scratch (allowed: __device__ globals; zero-init on load)
__device__ __align__(256) __half g_bufX[TOTAL_F];   // fp16 inputs, 153.6 MB
__device__ __align__(256) __half g_bufA[TOTAL_F];
__device__ __align__(256) __half g_bufB[TOTAL_F];
__device__ int  g_count[N_NODES];    // re-zeroed every replay by scan1
__device__ int  g_offsetL[N_NODES];  // block-local exclusive scan
__device__ int  g_pos[N_NODES];
__device__ int  g_bsum[SCAN_BLOCK];  // >= N_SCAN_BLOCKS
__device__ int2 g_pair[N_EDGES];     // (col, val-as-int), CSR order

// ---------------------------------------------------------------------------
// Launch 1: histogram (4 edges/thread, int4 loads) + fp32->fp16 conversion
// ---------------------------------------------------------------------------
__global__ void hist_convert_kernel(const int4* __restrict__ rows4,
                                    int* __restrict__ count,
                                    const float4* __restrict__ user,
                                    const float4* __restrict__ item,
                                    uint2* __restrict__ X2) {
    size_t tid = (size_t)blockIdx.x * blockDim.x + threadIdx.x;
    if (tid < N_EDGES / 4) {
        int4 r4 = __ldcs(rows4 + tid);
        atomicAdd(&count[r4.x], 1);
        atomicAdd(&count[r4.y], 1);
        atomicAdd(&count[r4.z], 1);
        atomicAdd(&count[r4.w], 1);
    }
    const size_t user_v4 = (size_t)N_USERS * VEC4_PER_ROW;
    size_t stride = (size_t)gridDim.x * blockDim.x;
    for (size_t i = tid; i < TOTAL_V4; i += stride) {
        float4 v = (i < user_v4) ? __ldcs(user + i) : __ldcs(item + i - user_v4);
        __half2 h0 = __floats2half2_rn(v.x, v.y);
        __half2 h1 = __floats2half2_rn(v.z, v.w);
        uint2 raw;
        raw.x = *reinterpret_cast<unsigned*>(&h0);
        raw.y = *reinterpret_cast<unsigned*>(&h1);
        __stcs(X2 + i, raw);   // streaming
    }
}

// ---------------------------------------------------------------------------
// Launch 2: block-local exclusive scan; zeroes count; seeds pos
// ---------------------------------------------------------------------------
__global__ void scan1_kernel(int* __restrict__ count,
                             int* __restrict__ offsetL,
                             int* __restrict__ pos,
                             int* __restrict__ bsum) {
    __shared__ int sh[SCAN_BLOCK];
    int i = blockIdx.x * SCAN_BLOCK + threadIdx.x;
    int v = (i < N_NODES) ? count[i] : 0;
    if (i < N_NODES) count[i] = 0;   // restore replay invariant
    sh[threadIdx.x] = v;
    __syncthreads();
    #pragma unroll
    for (int d = 1; d < SCAN_BLOCK; d <<= 1) {
        int t = (threadIdx.x >= d) ? sh[threadIdx.x - d] : 0;
        __syncthreads();
        sh[threadIdx.x] += t;
        __syncthreads();
    }
    if (i < N_NODES) {
        int excl = sh[threadIdx.x] - v;
        offsetL[i] = excl;
        pos[i] = excl;
    }
    if (threadIdx.x == SCAN_BLOCK - 1) bsum[blockIdx.x] = sh[SCAN_BLOCK - 1];
}

// ---------------------------------------------------------------------------
// Launch 3: exclusive scan of block sums (single block)
// ---------------------------------------------------------------------------
__global__ void scan2_kernel(int* __restrict__ bsum, int nb) {
    __shared__ int sh[SCAN_BLOCK];
    int v = (threadIdx.x < nb) ? bsum[threadIdx.x] : 0;
    sh[threadIdx.x] = v;
    __syncthreads();
    #pragma unroll
    for (int d = 1; d < SCAN_BLOCK; d <<= 1) {
        int t = (threadIdx.x >= d) ? sh[threadIdx.x - d] : 0;
        __syncthreads();
        sh[threadIdx.x] += t;
        __syncthreads();
    }
    if (threadIdx.x < nb) bsum[threadIdx.x] = sh[threadIdx.x] - v;  // exclusive
}

// ---------------------------------------------------------------------------
// Launch 4: permute, 4 edges/thread (int4/float4 loads, 4 independent chains)
// ---------------------------------------------------------------------------
__global__ void permute_kernel(const int4* __restrict__ rows4,
                               const int4* __restrict__ cols4,
                               const float4* __restrict__ vals4,
                               int* __restrict__ pos,
                               const int* __restrict__ bsum,
                               int2* __restrict__ pair) {
    int t = blockIdx.x * blockDim.x + threadIdx.x;
    if (t >= N_EDGES / 4) return;
    int4 r4 = __ldcs(rows4 + t);
    int4 c4 = __ldcs(cols4 + t);
    float4 v4 = __ldcs(vals4 + t);

    int p0 = atomicAdd(&pos[r4.x], 1) + __ldg(&bsum[r4.x >> 10]);
    int p1 = atomicAdd(&pos[r4.y], 1) + __ldg(&bsum[r4.y >> 10]);
    int p2 = atomicAdd(&pos[r4.z], 1) + __ldg(&bsum[r4.z >> 10]);
    int p3 = atomicAdd(&pos[r4.w], 1) + __ldg(&bsum[r4.w >> 10]);

    int2 e;
    e.x = c4.x; e.y = __float_as_int(v4.x); __stcs(pair + p0, e);
    e.x = c4.y; e.y = __float_as_int(v4.y); __stcs(pair + p1, e);
    e.x = c4.z; e.y = __float_as_int(v4.z); __stcs(pair + p2, e);
    e.x = c4.w; e.y = __float_as_int(v4.w); __stcs(pair + p3, e);
}

// ---------------------------------------------------------------------------
// Gather: 32B (256-bit) load with L2 evict_last, unpack 16 halfs, FMA.
// (Exact R9 form.)
// ---------------------------------------------------------------------------
__device__ __forceinline__ void gather_acc(const __half* __restrict__ srcH,
                                           int col, int sub, float v,
                                           float* acc) {
    const char* p = reinterpret_cast<const char*>(srcH)
                    + ((size_t)col << 8) + (sub << 5);
    uint32_t q0, q1, q2, q3, q4, q5, q6, q7;
    asm volatile(
        "ld.global.nc.L2::evict_last.v8.b32 {%0,%1,%2,%3,%4,%5,%6,%7}, [%8];"
        : "=r"(q0), "=r"(q1), "=r"(q2), "=r"(q3),
          "=r"(q4), "=r"(q5), "=r"(q6), "=r"(q7)
        : "l"(p));
    uint32_t q[8] = {q0, q1, q2, q3, q4, q5, q6, q7};
    #pragma unroll
    for (int i = 0; i < 8; ++i) {
        __half2 h = *reinterpret_cast<__half2*>(&q[i]);
        float2 f = __half22float2(h);
        acc[2 * i]     += v * f.x;
        acc[2 * i + 1] += v * f.y;
    }
}

__device__ __forceinline__ void unpack16(uint4 lo, uint4 hi, float* f) {
    uint32_t q[8] = {lo.x, lo.y, lo.z, lo.w, hi.x, hi.y, hi.z, hi.w};
    #pragma unroll
    for (int i = 0; i < 8; ++i) {
        __half2 h = *reinterpret_cast<__half2*>(&q[i]);
        float2 t = __half22float2(h);
        f[2 * i] = t.x;
        f[2 * i + 1] = t.y;
    }
}

// ---------------------------------------------------------------------------
// Launches 5-7: pull SpMM — EXACT R9 configuration. 8-lane group per row,
// lane owns 16 elements (32B fp16), x2 unroll + remainder, evict_last.
// FUSED (layer 3): out = 0.25*(x0_fp32 + A + B + y)
// ---------------------------------------------------------------------------
template <bool FUSED>
__global__ void __launch_bounds__(256)
spmm_kernel(const int* __restrict__ offsetL,
            const int* __restrict__ bsum,
            const int2* __restrict__ pair,
            const __half* __restrict__ xH,    // gather src (fp16, L2-pinned)
            __half* __restrict__ dstH,        // layer output (fp16)
            const float4* __restrict__ u,     // FUSED: user embs fp32
            const float4* __restrict__ it,    // FUSED: item embs fp32
            const __half* __restrict__ accA,  // FUSED: layer-1 out
            const __half* __restrict__ accB,  // FUSED: layer-2 out
            float4* __restrict__ out) {       // FUSED: final out fp32
    int sub = threadIdx.x & 7;                            // lane within group
    int r = (blockIdx.x * blockDim.x + threadIdx.x) >> 3; // group id = row
    if (r >= N_NODES) return;

    int j = __ldg(offsetL + r) + __ldg(bsum + (r >> 10));
    int end = (r == N_NODES - 1)
                  ? N_EDGES
                  : __ldg(offsetL + r + 1) + __ldg(bsum + ((r + 1) >> 10));

    float acc[16];
    #pragma unroll
    for (int k = 0; k < 16; ++k) acc[k] = 0.f;

    #pragma unroll 1
    for (; j + 2 <= end; j += 2) {
        int2 e0 = __ldcs(pair + j);        // 8 lanes same addr: broadcast
        int2 e1 = __ldcs(pair + j + 1);
        gather_acc(xH, e0.x, sub, __int_as_float(e0.y), acc);
        gather_acc(xH, e1.x, sub, __int_as_float(e1.y), acc);
    }
    if (j < end) {
        int2 e0 = __ldcs(pair + j);
        gather_acc(xH, e0.x, sub, __int_as_float(e0.y), acc);
    }

    if (FUSED) {
        const uint4* aRow = reinterpret_cast<const uint4*>(accA + (size_t)r * EMB_DIM);
        const uint4* bRow = reinterpret_cast<const uint4*>(accB + (size_t)r * EMB_DIM);
        float a[16], b[16];
        unpack16(__ldcs(aRow + 2 * sub), __ldcs(aRow + 2 * sub + 1), a);
        unpack16(__ldcs(bRow + 2 * sub), __ldcs(bRow + 2 * sub + 1), b);

        const float4* xr = (r < N_USERS)
                               ? (u + (size_t)r * VEC4_PER_ROW)
                               : (it + (size_t)(r - N_USERS) * VEC4_PER_ROW);
        float4* orow = out + (size_t)r * VEC4_PER_ROW + 4 * sub;
        #pragma unroll
        for (int q = 0; q < 4; ++q) {
            float4 x0 = __ldcs(xr + 4 * sub + q);
            float4 o;
            o.x = 0.25f * (x0.x + a[4 * q + 0] + b[4 * q + 0] + acc[4 * q + 0]);
            o.y = 0.25f * (x0.y + a[4 * q + 1] + b[4 * q + 1] + acc[4 * q + 1]);
            o.z = 0.25f * (x0.z + a[4 * q + 2] + b[4 * q + 2] + acc[4 * q + 2]);
            o.w = 0.25f * (x0.w + a[4 * q + 3] + b[4 * q + 3] + acc[4 * q + 3]);
            __stcs(orow + q, o);
        }
    } else {
        uint32_t q[8];
        #pragma unroll
        for (int i = 0; i < 8; ++i) {
            __half2 h = __floats2half2_rn(acc[2 * i], acc[2 * i + 1]);
            q[i] = *reinterpret_cast<unsigned*>(&h);
        }
        uint4* drow = reinterpret_cast<uint4*>(dstH + (size_t)r * EMB_DIM) + 2 * sub;
        __stcs(drow, make_uint4(q[0], q[1], q[2], q[3]));
        __stcs(drow + 1, make_uint4(q[4], q[5], q[6], q[7]));
    }
}

extern "C" void kernel_launch(void* const* d_in, const int* in_sizes, int n_in,
                              void* d_out, int out_size) {
    const float4* emb_user = (const float4*)d_in[0];
    const float4* emb_item = (const float4*)d_in[1];
    const int* edge_row = (const int*)d_in[2];
    const int* edge_col = (const int*)d_in[3];
    const float* edge_val = (const float*)d_in[4];
    float4* out = (float4*)d_out;

    __half *X, *A, *B;
    int *count_, *offsetL_, *pos_, *bsum_;
    int2 *pair_;
    cudaGetSymbolAddress((void**)&X, g_bufX);
    cudaGetSymbolAddress((void**)&A, g_bufA);
    cudaGetSymbolAddress((void**)&B, g_bufB);
    cudaGetSymbolAddress((void**)&count_, g_count);
    cudaGetSymbolAddress((void**)&offsetL_, g_offsetL);
    cudaGetSymbolAddress((void**)&pos_, g_pos);
    cudaGetSymbolAddress((void**)&bsum_, g_bsum);
    cudaGetSymbolAddress((void**)&pair_, g_pair);

    const int T = 256;
    const int gridEdge4 = (N_EDGES / 4 + T - 1) / T;      // 4 edges/thread
    const int TS = 256;                                   // 32 rows per block
    const int gridRow = (int)(((size_t)N_NODES * 8 + TS - 1) / TS);

    // ---- build: histogram(+convert), two-kernel scan, permute ----
    hist_convert_kernel<<<gridEdge4 * 4, T>>>((const int4*)edge_row, count_,
                                              emb_user, emb_item, (uint2*)X);
    scan1_kernel<<<N_SCAN_BLOCKS, SCAN_BLOCK>>>(count_, offsetL_, pos_, bsum_);
    scan2_kernel<<<1, SCAN_BLOCK>>>(bsum_, N_SCAN_BLOCKS);
    permute_kernel<<<gridEdge4, T>>>((const int4*)edge_row,
                                     (const int4*)edge_col,
                                     (const float4*)edge_val,
                                     pos_, bsum_, pair_);

    // ---- Layer 1: gather X -> A ----
    spmm_kernel<false><<<gridRow, TS>>>(offsetL_, bsum_, pair_, X, A,
                                        nullptr, nullptr, nullptr, nullptr,
                                        nullptr);
    // ---- Layer 2: gather A -> B ----
    spmm_kernel<false><<<gridRow, TS>>>(offsetL_, bsum_, pair_, A, B,
                                        nullptr, nullptr, nullptr, nullptr,
                                        nullptr);
    // ---- Layer 3 fused: gather B, out = 0.25*(x0 + A + B + y) ----
    spmm_kernel<true><<<gridRow, TS>>>(offsetL_, bsum_, pair_, B, nullptr,
                                       emb_user, emb_item, A, B, out);
}